// round 10
// baseline (speedup 1.0000x reference)
#include <cuda_runtime.h>

// x: [B=16, C=256, H=32, W=32] viewed [BC=4096][HW=1024].
// x1[b,p,cij] = x[b,cij,p]; 30 layers of per-channel(p) BN+relu6 ODE.
// TWO channels per CTA (grid 512): doubles per-thread ILP across the
// per-layer reduce/rsqrt dependency chain and cuts waves 1.73 -> 1.15.
// z̃ = z/alpha recursion; f32x2 packed math; relu6 via FFMA.SAT;
// one barrier per layer with double-buffered float4 reduction slots.

constexpr int HW = 1024;
constexpr int BC = 4096;
constexpr int NL = 30;

__device__ float g_xt[(size_t)HW * BC];
__device__ float g_yt[(size_t)HW * BC];

typedef unsigned long long u64;

__device__ __forceinline__ u64 pk2(float x, float y) {
    u64 r; asm("mov.b64 %0,{%1,%2};" : "=l"(r) : "f"(x), "f"(y)); return r;
}
__device__ __forceinline__ void upk2(u64 v, float& x, float& y) {
    asm("mov.b64 {%0,%1},%2;" : "=f"(x), "=f"(y) : "l"(v));
}
__device__ __forceinline__ u64 fma2(u64 a, u64 b, u64 c) {
    u64 d; asm("fma.rn.f32x2 %0,%1,%2,%3;" : "=l"(d) : "l"(a), "l"(b), "l"(c)); return d;
}
__device__ __forceinline__ u64 add2(u64 a, u64 b) {
    u64 d; asm("add.rn.f32x2 %0,%1,%2;" : "=l"(d) : "l"(a), "l"(b)); return d;
}
__device__ __forceinline__ u64 mul2(u64 a, u64 b) {
    u64 d; asm("mul.rn.f32x2 %0,%1,%2;" : "=l"(d) : "l"(a), "l"(b)); return d;
}
__device__ __forceinline__ float fma_sat(float a, float b, float c) {
    float d; asm("fma.rn.sat.f32 %0,%1,%2,%3;" : "=f"(d) : "f"(a), "f"(b), "f"(c)); return d;
}

// ---------------------------------------------------------------------------
// Scalar 32x32 tiled transpose (proven): out[c][r] = in[r][c]
// ---------------------------------------------------------------------------
template<int ROWS, int COLS>
__global__ __launch_bounds__(256) void tr_kernel(const float* __restrict__ in,
                                                 float* __restrict__ out) {
    __shared__ float tile[32][33];
    const int bx = blockIdx.x * 32;
    const int by = blockIdx.y * 32;
    const int tx = threadIdx.x, ty = threadIdx.y;
#pragma unroll
    for (int j = 0; j < 32; j += 8)
        tile[ty + j][tx] = in[(size_t)(by + ty + j) * COLS + (bx + tx)];
    __syncthreads();
#pragma unroll
    for (int j = 0; j < 32; j += 8)
        out[(size_t)(bx + ty + j) * ROWS + (by + tx)] = tile[tx][ty + j];
}

// ---------------------------------------------------------------------------
// Fused 30-layer ODE, 2 channels per CTA. 256 threads; thread t owns
// (cij=t, b=0..15) for channels pA = 2*bid and pB = 2*bid+1 (8 packed
// pairs each). One barrier per layer; float4 reduction slots carry both
// channels' (sum, sumsq).
// ---------------------------------------------------------------------------
__global__ __launch_bounds__(256, 3) void ode_kernel(
    const float* __restrict__ xt,        // [HW][BC]
    const float* __restrict__ dtg,       // [NL]
    const float* __restrict__ mats,      // [NL][256]
    const float* __restrict__ gamma,     // [HW]
    const float* __restrict__ beta,      // [HW]
    float* __restrict__ yt)              // [HW][BC]
{
    __shared__ float4 lay[NL];           // {c1_l, A_{l+1}, 6*dt_l*A_{l+1}, eps*A_l^2}
    __shared__ float4 red[2][8];         // {sA, qA, sB, qB} per warp
    __shared__ float  sm_alpha;

    const int pA = blockIdx.x * 2;
    const int pB = pA + 1;
    const int t = threadIdx.x;
    const int lane = t & 31;
    const int wid  = t >> 5;

    // --- per-layer scalar precompute ---
    if (t < NL) {
        float d = dtg[t];
        d = fminf(fmaxf(d, 0.0f), 6.0f);
        lay[t].x = 1.0f - d;             // c1
        lay[t].y = d;                    // stash dt
    }
    __syncthreads();
    if (t == 0) {
        float A = 1.0f;                  // 1/alpha running
        float P = 1.0f;                  // alpha running (prod c1)
        for (int l = 0; l < NL; ++l) {
            const float c1 = lay[l].x;
            const float d  = lay[l].y;
            const float eps = 1e-5f * A * A;
            const float An = __fdividef(A, c1);
            P *= c1;
            lay[l] = make_float4(c1, An, 6.0f * d * An, eps);
            A = An;
        }
        sm_alpha = P;
    }

    const float gmA = gamma[pA], btA = beta[pA];
    const float gmB = gamma[pB], btB = beta[pB];
    const float* __restrict__ xpA = xt + (size_t)pA * BC + t;
    const float* __restrict__ xpB = xt + (size_t)pB * BC + t;
    const float* __restrict__ mp  = mats + t;

    // --- load x1 to registers, init z̃_1 = (1+m_0)*x1 ---
    float mt = mp[0];
    u64 x1a[8], za[8], x1b[8], zb[8];
#pragma unroll
    for (int u = 0; u < 8; ++u) {
        const float a0 = xpA[(2 * u) * 256];
        const float a1 = xpA[(2 * u + 1) * 256];
        x1a[u] = pk2(a0, a1);
        za[u]  = pk2(fmaf(mt, a0, a0), fmaf(mt, a1, a1));
        const float b0 = xpB[(2 * u) * 256];
        const float b1 = xpB[(2 * u + 1) * 256];
        x1b[u] = pk2(b0, b1);
        zb[u]  = pk2(fmaf(mt, b0, b0), fmaf(mt, b1, b1));
    }
    __syncthreads();                      // covers lay[] / sm_alpha from t==0

    for (int l = 0; l < NL; ++l) {
        const float4 L = lay[l];          // LDS.128 broadcast
        const float mnx = (l < NL - 1) ? mp[(l + 1) * 256] : 1.0f;
        const float kps = fmaf(-L.x, mt, mnx) * L.y;   // (m' - c1*m) * A_{l+1}
        mt = mnx;
        const u64 kp   = pk2(kps, kps);
        const u64 dt6p = pk2(L.z, L.z);
        const int par  = l & 1;

        // stats on z̃ for both channels (packed accumulate)
        u64 sa = 0ull, qa = 0ull, sb = 0ull, qb = 0ull;
#pragma unroll
        for (int u = 0; u < 8; ++u) {
            sa = add2(sa, za[u]);
            qa = fma2(za[u], za[u], qa);
            sb = add2(sb, zb[u]);
            qb = fma2(zb[u], zb[u], qb);
        }
        float t0, t1;
        upk2(sa, t0, t1); float sA = t0 + t1;
        upk2(qa, t0, t1); float qA = t0 + t1;
        upk2(sb, t0, t1); float sB = t0 + t1;
        upk2(qb, t0, t1); float qB = t0 + t1;
#pragma unroll
        for (int o = 16; o > 0; o >>= 1) {
            sA += __shfl_xor_sync(0xffffffffu, sA, o);
            qA += __shfl_xor_sync(0xffffffffu, qA, o);
            sB += __shfl_xor_sync(0xffffffffu, sB, o);
            qB += __shfl_xor_sync(0xffffffffu, qB, o);
        }
        if (lane == 0) red[par][wid] = make_float4(sA, qA, sB, qB);
        __syncthreads();                  // the ONLY barrier this layer

        // redundant all-warp final reduce from the 8 warp partials
        const float4 rv = red[par][lane & 7];
        float SA = rv.x, QA = rv.y, SB = rv.z, QB = rv.w;
#pragma unroll
        for (int o = 4; o > 0; o >>= 1) {
            SA += __shfl_xor_sync(0xffffffffu, SA, o);
            QA += __shfl_xor_sync(0xffffffffu, QA, o);
            SB += __shfl_xor_sync(0xffffffffu, SB, o);
            QB += __shfl_xor_sync(0xffffffffu, QB, o);
        }
        const float inv = 1.0f / 4096.0f;
        const float muA = SA * inv;
        const float vaA = fmaf(-muA, muA, QA * inv);
        const float apA = gmA * rsqrtf(vaA + L.w);
        const float a6A = apA * (1.0f / 6.0f);
        const float b6A = fmaf(-muA, apA, btA) * (1.0f / 6.0f);
        const float muB = SB * inv;
        const float vaB = fmaf(-muB, muB, QB * inv);
        const float apB = gmB * rsqrtf(vaB + L.w);
        const float a6B = apB * (1.0f / 6.0f);
        const float b6B = fmaf(-muB, apB, btB) * (1.0f / 6.0f);

#pragma unroll
        for (int u = 0; u < 8; ++u) {
            float zx, zy;
            upk2(za[u], zx, zy);
            const float rax = fma_sat(zx, a6A, b6A);   // relu6/6 via FFMA.SAT
            const float ray = fma_sat(zy, a6A, b6A);
            za[u] = fma2(dt6p, pk2(rax, ray), za[u]);
            za[u] = fma2(kp, x1a[u], za[u]);
            upk2(zb[u], zx, zy);
            const float rbx = fma_sat(zx, a6B, b6B);
            const float rby = fma_sat(zy, a6B, b6B);
            zb[u] = fma2(dt6p, pk2(rbx, rby), zb[u]);
            zb[u] = fma2(kp, x1b[u], zb[u]);
        }
    }

    // out = alpha * z̃_final  (layer 29 used m'=1 so z̃ holds y + x1)
    const float al = sm_alpha;
    const u64 al2 = pk2(al, al);
    float* __restrict__ ypA = yt + (size_t)pA * BC + t;
    float* __restrict__ ypB = yt + (size_t)pB * BC + t;
#pragma unroll
    for (int u = 0; u < 8; ++u) {
        float ox, oy;
        upk2(mul2(za[u], al2), ox, oy);
        ypA[(2 * u) * 256]     = ox;
        ypA[(2 * u + 1) * 256] = oy;
        upk2(mul2(zb[u], al2), ox, oy);
        ypB[(2 * u) * 256]     = ox;
        ypB[(2 * u + 1) * 256] = oy;
    }
}

// ---------------------------------------------------------------------------
extern "C" void kernel_launch(void* const* d_in, const int* in_sizes, int n_in,
                              void* d_out, int out_size) {
    const float* x   = (const float*)d_in[0];   // [16,256,32,32]
    const float* dt  = (const float*)d_in[1];   // [30,1]
    const float* mat = (const float*)d_in[2];   // [30,1,1,16,16]
    const float* gm  = (const float*)d_in[3];   // [1024]
    const float* bt  = (const float*)d_in[4];   // [1024]
    float* out = (float*)d_out;                 // [16,256,32,32]

    float *xt, *yt;
    cudaGetSymbolAddress((void**)&xt, g_xt);
    cudaGetSymbolAddress((void**)&yt, g_yt);

    dim3 blk(32, 8);
    // x: [4096 x 1024] -> xt: [1024 x 4096]
    tr_kernel<BC, HW><<<dim3(HW / 32, BC / 32), blk>>>(x, xt);
    // fused 30-layer ODE, two channels per CTA
    ode_kernel<<<HW / 2, 256>>>(xt, dt, mat, gm, bt, yt);
    // yt: [1024 x 4096] -> out: [4096 x 1024]
    tr_kernel<HW, BC><<<dim3(BC / 32, HW / 32), blk>>>(yt, out);
}

// round 11
// speedup vs baseline: 1.3224x; 1.3224x over previous
#include <cuda_runtime.h>

// x: [B=16, C=256, H=32, W=32] viewed [BC=4096][HW=1024].
// x1[b,p,cij] = x[b,cij,p]; 30 layers of per-channel(p) BN+relu6 ODE.
// ODE: round-9 proven version (one CTA/channel, occ 4, f32x2 + FFMA.SAT,
// one barrier/layer). Transposes: float2 64x32 tiles with EVEN row stride
// (66 floats) so all st.shared.v2 are 8B-aligned; writes conflict-free,
// reads 2-way (acceptable; kernel is gmem-latency bound).

constexpr int HW = 1024;
constexpr int BC = 4096;
constexpr int NL = 30;

__device__ float g_xt[(size_t)HW * BC];
__device__ float g_yt[(size_t)HW * BC];

typedef unsigned long long u64;

__device__ __forceinline__ u64 pk2(float x, float y) {
    u64 r; asm("mov.b64 %0,{%1,%2};" : "=l"(r) : "f"(x), "f"(y)); return r;
}
__device__ __forceinline__ void upk2(u64 v, float& x, float& y) {
    asm("mov.b64 {%0,%1},%2;" : "=f"(x), "=f"(y) : "l"(v));
}
__device__ __forceinline__ u64 fma2(u64 a, u64 b, u64 c) {
    u64 d; asm("fma.rn.f32x2 %0,%1,%2,%3;" : "=l"(d) : "l"(a), "l"(b), "l"(c)); return d;
}
__device__ __forceinline__ u64 add2(u64 a, u64 b) {
    u64 d; asm("add.rn.f32x2 %0,%1,%2;" : "=l"(d) : "l"(a), "l"(b)); return d;
}
__device__ __forceinline__ u64 mul2(u64 a, u64 b) {
    u64 d; asm("mul.rn.f32x2 %0,%1,%2;" : "=l"(d) : "l"(a), "l"(b)); return d;
}
__device__ __forceinline__ float fma_sat(float a, float b, float c) {
    float d; asm("fma.rn.sat.f32 %0,%1,%2,%3;" : "=f"(d) : "f"(a), "f"(b), "f"(c)); return d;
}

// ---------------------------------------------------------------------------
// float2 tiled transpose: in-tile 32 rows x 64 cols, out[c][r] = in[r][c].
// tile[32][66]: even stride -> aligned float2 smem writes; write banks
// 2tx%32 distinct per half-warp (conflict-free); read 2-way conflicted.
// ---------------------------------------------------------------------------
template<int ROWS, int COLS>
__global__ __launch_bounds__(256) void tr2_kernel(const float* __restrict__ in,
                                                  float* __restrict__ out) {
    __shared__ float tile[32][66];
    const int bx = blockIdx.x * 64;           // column base (in)
    const int by = blockIdx.y * 32;           // row base (in)
    const int t  = threadIdx.x;

    {
        const int tx = t & 31;                // float2 index across 64 cols
        const int ty = t >> 5;                // 8 rows per step
#pragma unroll
        for (int j = 0; j < 32; j += 8) {
            const float2 v = *reinterpret_cast<const float2*>(
                in + (size_t)(by + ty + j) * COLS + bx + tx * 2);
            *reinterpret_cast<float2*>(&tile[ty + j][tx * 2]) = v;   // aligned: stride 66 even
        }
    }
    __syncthreads();
    {
        const int tx = t & 15;                // float2 index across 32 out-cols
        const int ty = t >> 4;                // 16 out-rows per step
#pragma unroll
        for (int j = 0; j < 64; j += 16) {
            const int r = ty + j;             // out row = in col offset
            float2 v;
            v.x = tile[tx * 2 + 0][r];
            v.y = tile[tx * 2 + 1][r];
            *reinterpret_cast<float2*>(
                out + (size_t)(bx + r) * ROWS + by + tx * 2) = v;    // ROWS,by even
        }
    }
}

// ---------------------------------------------------------------------------
// Fused 30-layer ODE (round-9 proven). One CTA per channel p, 256 threads.
// Thread t owns (cij=t, b=0..15) as 8 packed pairs; x1 and z in registers.
// One __syncthreads per layer; redundant all-warp final reduce from
// double-buffered red[l&1][8].
// ---------------------------------------------------------------------------
__global__ __launch_bounds__(256, 4) void ode_kernel(
    const float* __restrict__ xt,        // [HW][BC]
    const float* __restrict__ dtg,       // [NL]
    const float* __restrict__ mats,      // [NL][256]
    const float* __restrict__ gamma,     // [HW]
    const float* __restrict__ beta,      // [HW]
    float* __restrict__ yt)              // [HW][BC]
{
    __shared__ float4 lay[NL];           // {c1_l, A_{l+1}, 6*dt_l*A_{l+1}, eps*A_l^2}
    __shared__ float2 red[2][8];
    __shared__ float  sm_alpha;

    const int p = blockIdx.x;
    const int t = threadIdx.x;
    const int lane = t & 31;
    const int wid  = t >> 5;

    // --- per-layer scalar precompute ---
    if (t < NL) {
        float d = dtg[t];
        d = fminf(fmaxf(d, 0.0f), 6.0f);
        lay[t].x = 1.0f - d;             // c1
        lay[t].y = d;                    // stash dt
    }
    __syncthreads();
    if (t == 0) {
        float A = 1.0f;                  // 1/alpha running
        float P = 1.0f;                  // alpha running (prod c1)
        for (int l = 0; l < NL; ++l) {
            const float c1 = lay[l].x;
            const float d  = lay[l].y;
            const float eps = 1e-5f * A * A;
            const float An = __fdividef(A, c1);
            P *= c1;
            lay[l] = make_float4(c1, An, 6.0f * d * An, eps);
            A = An;
        }
        sm_alpha = P;
    }

    const float gm = gamma[p];
    const float bt = beta[p];
    const float* __restrict__ xp = xt + (size_t)p * BC + t;
    const float* __restrict__ mp = mats + t;

    // --- load x1 to registers, init z̃_1 = (1+m_0)*x1 ---
    float mt = mp[0];
    u64 x1[8], z[8];
#pragma unroll
    for (int u = 0; u < 8; ++u) {
        const float a = xp[(2 * u) * 256];
        const float b = xp[(2 * u + 1) * 256];
        x1[u] = pk2(a, b);
        z[u]  = pk2(fmaf(mt, a, a), fmaf(mt, b, b));
    }
    __syncthreads();                      // covers lay[] / sm_alpha from t==0

    for (int l = 0; l < NL; ++l) {
        const float4 L = lay[l];          // LDS.128 broadcast
        const float mnx = (l < NL - 1) ? mp[(l + 1) * 256] : 1.0f;
        const float kps = fmaf(-L.x, mt, mnx) * L.y;   // (m' - c1*m) * A_{l+1}
        mt = mnx;
        const u64 kp   = pk2(kps, kps);
        const u64 dt6p = pk2(L.z, L.z);
        const int par  = l & 1;

        // stats on z̃ (packed accumulate)
        u64 s2 = 0ull, q2 = 0ull;
#pragma unroll
        for (int u = 0; u < 8; ++u) {
            s2 = add2(s2, z[u]);
            q2 = fma2(z[u], z[u], q2);
        }
        float sx, sy, qx, qy;
        upk2(s2, sx, sy); upk2(q2, qx, qy);
        float s = sx + sy, q = qx + qy;
#pragma unroll
        for (int o = 16; o > 0; o >>= 1) {
            s += __shfl_xor_sync(0xffffffffu, s, o);
            q += __shfl_xor_sync(0xffffffffu, q, o);
        }
        if (lane == 0) red[par][wid] = make_float2(s, q);
        __syncthreads();                  // the ONLY barrier this layer

        // redundant all-warp final reduce from the 8 warp partials
        const float2 rv = red[par][lane & 7];
        float S = rv.x, Q = rv.y;
#pragma unroll
        for (int o = 4; o > 0; o >>= 1) {
            S += __shfl_xor_sync(0xffffffffu, S, o);
            Q += __shfl_xor_sync(0xffffffffu, Q, o);
        }
        const float inv = 1.0f / 4096.0f;
        const float mu  = S * inv;
        const float va  = fmaf(-mu, mu, Q * inv);
        const float ap  = gm * rsqrtf(va + L.w);
        const float a6  = ap * (1.0f / 6.0f);
        const float b6  = fmaf(-mu, ap, bt) * (1.0f / 6.0f);

#pragma unroll
        for (int u = 0; u < 8; ++u) {
            float zx, zy; upk2(z[u], zx, zy);
            const float rx = fma_sat(zx, a6, b6);      // relu6/6 via FFMA.SAT
            const float ry = fma_sat(zy, a6, b6);
            z[u] = fma2(dt6p, pk2(rx, ry), z[u]);
            z[u] = fma2(kp, x1[u], z[u]);
        }
    }

    // out = alpha * z̃_final  (layer 29 used m'=1 so z̃ holds y + x1)
    const float al = sm_alpha;
    const u64 al2 = pk2(al, al);
    float* __restrict__ yp = yt + (size_t)p * BC + t;
#pragma unroll
    for (int u = 0; u < 8; ++u) {
        float ox, oy; upk2(mul2(z[u], al2), ox, oy);
        yp[(2 * u) * 256]     = ox;
        yp[(2 * u + 1) * 256] = oy;
    }
}

// ---------------------------------------------------------------------------
extern "C" void kernel_launch(void* const* d_in, const int* in_sizes, int n_in,
                              void* d_out, int out_size) {
    const float* x   = (const float*)d_in[0];   // [16,256,32,32]
    const float* dt  = (const float*)d_in[1];   // [30,1]
    const float* mat = (const float*)d_in[2];   // [30,1,1,16,16]
    const float* gm  = (const float*)d_in[3];   // [1024]
    const float* bt  = (const float*)d_in[4];   // [1024]
    float* out = (float*)d_out;                 // [16,256,32,32]

    float *xt, *yt;
    cudaGetSymbolAddress((void**)&xt, g_xt);
    cudaGetSymbolAddress((void**)&yt, g_yt);

    // x: [4096 x 1024] -> xt: [1024 x 4096]
    tr2_kernel<BC, HW><<<dim3(HW / 64, BC / 32), 256>>>(x, xt);
    // fused 30-layer ODE, one CTA per channel (round-9 proven)
    ode_kernel<<<HW, 256>>>(xt, dt, mat, gm, bt, yt);
    // yt: [1024 x 4096] -> out: [4096 x 1024]
    tr2_kernel<HW, BC><<<dim3(BC / 64, HW / 32), 256>>>(yt, out);
}

// round 12
// speedup vs baseline: 1.3663x; 1.0332x over previous
#include <cuda_runtime.h>

// x: [B=16, C=256, H=32, W=32] viewed [BC=4096][HW=1024].
// x1[b,p,cij] = x[b,cij,p]; 30 layers of per-channel(p) BN+relu6 ODE.
// ODE: round-9 proven version (one CTA/channel, occ 4, f32x2 + FFMA.SAT,
// one barrier/layer). Transposes: 64x64 float2 tiles (stride-66 smem, all
// st.shared.v2 aligned) -> 8 LDG.64 in flight per thread before the barrier.

constexpr int HW = 1024;
constexpr int BC = 4096;
constexpr int NL = 30;

__device__ float g_xt[(size_t)HW * BC];
__device__ float g_yt[(size_t)HW * BC];

typedef unsigned long long u64;

__device__ __forceinline__ u64 pk2(float x, float y) {
    u64 r; asm("mov.b64 %0,{%1,%2};" : "=l"(r) : "f"(x), "f"(y)); return r;
}
__device__ __forceinline__ void upk2(u64 v, float& x, float& y) {
    asm("mov.b64 {%0,%1},%2;" : "=f"(x), "=f"(y) : "l"(v));
}
__device__ __forceinline__ u64 fma2(u64 a, u64 b, u64 c) {
    u64 d; asm("fma.rn.f32x2 %0,%1,%2,%3;" : "=l"(d) : "l"(a), "l"(b), "l"(c)); return d;
}
__device__ __forceinline__ u64 add2(u64 a, u64 b) {
    u64 d; asm("add.rn.f32x2 %0,%1,%2;" : "=l"(d) : "l"(a), "l"(b)); return d;
}
__device__ __forceinline__ u64 mul2(u64 a, u64 b) {
    u64 d; asm("mul.rn.f32x2 %0,%1,%2;" : "=l"(d) : "l"(a), "l"(b)); return d;
}
__device__ __forceinline__ float fma_sat(float a, float b, float c) {
    float d; asm("fma.rn.sat.f32 %0,%1,%2,%3;" : "=f"(d) : "f"(a), "f"(b), "f"(c)); return d;
}

// ---------------------------------------------------------------------------
// float2 tiled transpose, 64x64 tiles: out[c][r] = in[r][c].
// tile[64][66]: even stride -> aligned float2 smem writes (proven pattern);
// 8 LDG.64 outstanding per thread before the single barrier.
// ---------------------------------------------------------------------------
template<int ROWS, int COLS>
__global__ __launch_bounds__(256) void tr64_kernel(const float* __restrict__ in,
                                                   float* __restrict__ out) {
    __shared__ float tile[64][66];
    const int bx = blockIdx.x * 64;           // column base (in)
    const int by = blockIdx.y * 64;           // row base (in)
    const int t  = threadIdx.x;

    {
        const int tx = t & 31;                // float2 index across 64 cols
        const int ty = t >> 5;                // 8 rows per step, 8 steps
#pragma unroll
        for (int j = 0; j < 64; j += 8) {
            const float2 v = *reinterpret_cast<const float2*>(
                in + (size_t)(by + ty + j) * COLS + bx + tx * 2);
            *reinterpret_cast<float2*>(&tile[ty + j][tx * 2]) = v;   // aligned (stride 66)
        }
    }
    __syncthreads();
    {
        const int tx = t & 15;                // float2 index (half of 32)
        const int ty = t >> 4;                // 16 out-rows per step
#pragma unroll
        for (int j = 0; j < 64; j += 16) {
            const int r = ty + j;             // out row = in col offset
#pragma unroll
            for (int h = 0; h < 2; ++h) {
                const int c2 = tx + 16 * h;   // float2 index over 64 out-cols
                float2 v;
                v.x = tile[c2 * 2 + 0][r];
                v.y = tile[c2 * 2 + 1][r];
                *reinterpret_cast<float2*>(
                    out + (size_t)(bx + r) * ROWS + by + c2 * 2) = v;
            }
        }
    }
}

// ---------------------------------------------------------------------------
// Fused 30-layer ODE (round-9 proven). One CTA per channel p, 256 threads.
// Thread t owns (cij=t, b=0..15) as 8 packed pairs; x1 and z in registers.
// One __syncthreads per layer; redundant all-warp final reduce from
// double-buffered red[l&1][8].
// ---------------------------------------------------------------------------
__global__ __launch_bounds__(256, 4) void ode_kernel(
    const float* __restrict__ xt,        // [HW][BC]
    const float* __restrict__ dtg,       // [NL]
    const float* __restrict__ mats,      // [NL][256]
    const float* __restrict__ gamma,     // [HW]
    const float* __restrict__ beta,      // [HW]
    float* __restrict__ yt)              // [HW][BC]
{
    __shared__ float4 lay[NL];           // {c1_l, A_{l+1}, 6*dt_l*A_{l+1}, eps*A_l^2}
    __shared__ float2 red[2][8];
    __shared__ float  sm_alpha;

    const int p = blockIdx.x;
    const int t = threadIdx.x;
    const int lane = t & 31;
    const int wid  = t >> 5;

    // --- per-layer scalar precompute ---
    if (t < NL) {
        float d = dtg[t];
        d = fminf(fmaxf(d, 0.0f), 6.0f);
        lay[t].x = 1.0f - d;             // c1
        lay[t].y = d;                    // stash dt
    }
    __syncthreads();
    if (t == 0) {
        float A = 1.0f;                  // 1/alpha running
        float P = 1.0f;                  // alpha running (prod c1)
        for (int l = 0; l < NL; ++l) {
            const float c1 = lay[l].x;
            const float d  = lay[l].y;
            const float eps = 1e-5f * A * A;
            const float An = __fdividef(A, c1);
            P *= c1;
            lay[l] = make_float4(c1, An, 6.0f * d * An, eps);
            A = An;
        }
        sm_alpha = P;
    }

    const float gm = gamma[p];
    const float bt = beta[p];
    const float* __restrict__ xp = xt + (size_t)p * BC + t;
    const float* __restrict__ mp = mats + t;

    // --- load x1 to registers, init z̃_1 = (1+m_0)*x1 ---
    float mt = mp[0];
    u64 x1[8], z[8];
#pragma unroll
    for (int u = 0; u < 8; ++u) {
        const float a = xp[(2 * u) * 256];
        const float b = xp[(2 * u + 1) * 256];
        x1[u] = pk2(a, b);
        z[u]  = pk2(fmaf(mt, a, a), fmaf(mt, b, b));
    }
    __syncthreads();                      // covers lay[] / sm_alpha from t==0

    for (int l = 0; l < NL; ++l) {
        const float4 L = lay[l];          // LDS.128 broadcast
        const float mnx = (l < NL - 1) ? mp[(l + 1) * 256] : 1.0f;
        const float kps = fmaf(-L.x, mt, mnx) * L.y;   // (m' - c1*m) * A_{l+1}
        mt = mnx;
        const u64 kp   = pk2(kps, kps);
        const u64 dt6p = pk2(L.z, L.z);
        const int par  = l & 1;

        // stats on z̃ (packed accumulate)
        u64 s2 = 0ull, q2 = 0ull;
#pragma unroll
        for (int u = 0; u < 8; ++u) {
            s2 = add2(s2, z[u]);
            q2 = fma2(z[u], z[u], q2);
        }
        float sx, sy, qx, qy;
        upk2(s2, sx, sy); upk2(q2, qx, qy);
        float s = sx + sy, q = qx + qy;
#pragma unroll
        for (int o = 16; o > 0; o >>= 1) {
            s += __shfl_xor_sync(0xffffffffu, s, o);
            q += __shfl_xor_sync(0xffffffffu, q, o);
        }
        if (lane == 0) red[par][wid] = make_float2(s, q);
        __syncthreads();                  // the ONLY barrier this layer

        // redundant all-warp final reduce from the 8 warp partials
        const float2 rv = red[par][lane & 7];
        float S = rv.x, Q = rv.y;
#pragma unroll
        for (int o = 4; o > 0; o >>= 1) {
            S += __shfl_xor_sync(0xffffffffu, S, o);
            Q += __shfl_xor_sync(0xffffffffu, Q, o);
        }
        const float inv = 1.0f / 4096.0f;
        const float mu  = S * inv;
        const float va  = fmaf(-mu, mu, Q * inv);
        const float ap  = gm * rsqrtf(va + L.w);
        const float a6  = ap * (1.0f / 6.0f);
        const float b6  = fmaf(-mu, ap, bt) * (1.0f / 6.0f);

#pragma unroll
        for (int u = 0; u < 8; ++u) {
            float zx, zy; upk2(z[u], zx, zy);
            const float rx = fma_sat(zx, a6, b6);      // relu6/6 via FFMA.SAT
            const float ry = fma_sat(zy, a6, b6);
            z[u] = fma2(dt6p, pk2(rx, ry), z[u]);
            z[u] = fma2(kp, x1[u], z[u]);
        }
    }

    // out = alpha * z̃_final  (layer 29 used m'=1 so z̃ holds y + x1)
    const float al = sm_alpha;
    const u64 al2 = pk2(al, al);
    float* __restrict__ yp = yt + (size_t)p * BC + t;
#pragma unroll
    for (int u = 0; u < 8; ++u) {
        float ox, oy; upk2(mul2(z[u], al2), ox, oy);
        yp[(2 * u) * 256]     = ox;
        yp[(2 * u + 1) * 256] = oy;
    }
}

// ---------------------------------------------------------------------------
extern "C" void kernel_launch(void* const* d_in, const int* in_sizes, int n_in,
                              void* d_out, int out_size) {
    const float* x   = (const float*)d_in[0];   // [16,256,32,32]
    const float* dt  = (const float*)d_in[1];   // [30,1]
    const float* mat = (const float*)d_in[2];   // [30,1,1,16,16]
    const float* gm  = (const float*)d_in[3];   // [1024]
    const float* bt  = (const float*)d_in[4];   // [1024]
    float* out = (float*)d_out;                 // [16,256,32,32]

    float *xt, *yt;
    cudaGetSymbolAddress((void**)&xt, g_xt);
    cudaGetSymbolAddress((void**)&yt, g_yt);

    // x: [4096 x 1024] -> xt: [1024 x 4096]
    tr64_kernel<BC, HW><<<dim3(HW / 64, BC / 64), 256>>>(x, xt);
    // fused 30-layer ODE, one CTA per channel (round-9 proven)
    ode_kernel<<<HW, 256>>>(xt, dt, mat, gm, bt, yt);
    // yt: [1024 x 4096] -> out: [4096 x 1024]
    tr64_kernel<HW, BC><<<dim3(BC / 64, HW / 64), 256>>>(yt, out);
}

// round 13
// speedup vs baseline: 1.4361x; 1.0511x over previous
#include <cuda_runtime.h>

// x: [B=16, C=256, H=32, W=32] viewed [BC=4096][HW=1024].
// ODE: round-9 proven core (one CTA/channel, occ 4, f32x2 + FFMA.SAT, one
// barrier/layer) with shortened shuffle trees (7+4 shfl via parity trick).
// Transposes: 64x64 float2 tiles, EXPLICIT two-phase batching (all LDG ->
// regs -> all STS; all LDS -> regs -> all STG) to maximize MLP_p1.

constexpr int HW = 1024;
constexpr int BC = 4096;
constexpr int NL = 30;

__device__ float g_xt[(size_t)HW * BC];
__device__ float g_yt[(size_t)HW * BC];

typedef unsigned long long u64;

__device__ __forceinline__ u64 pk2(float x, float y) {
    u64 r; asm("mov.b64 %0,{%1,%2};" : "=l"(r) : "f"(x), "f"(y)); return r;
}
__device__ __forceinline__ void upk2(u64 v, float& x, float& y) {
    asm("mov.b64 {%0,%1},%2;" : "=f"(x), "=f"(y) : "l"(v));
}
__device__ __forceinline__ u64 fma2(u64 a, u64 b, u64 c) {
    u64 d; asm("fma.rn.f32x2 %0,%1,%2,%3;" : "=l"(d) : "l"(a), "l"(b), "l"(c)); return d;
}
__device__ __forceinline__ u64 add2(u64 a, u64 b) {
    u64 d; asm("add.rn.f32x2 %0,%1,%2;" : "=l"(d) : "l"(a), "l"(b)); return d;
}
__device__ __forceinline__ u64 mul2(u64 a, u64 b) {
    u64 d; asm("mul.rn.f32x2 %0,%1,%2;" : "=l"(d) : "l"(a), "l"(b)); return d;
}
__device__ __forceinline__ float fma_sat(float a, float b, float c) {
    float d; asm("fma.rn.sat.f32 %0,%1,%2,%3;" : "=f"(d) : "f"(a), "f"(b), "f"(c)); return d;
}

// ---------------------------------------------------------------------------
// float2 tiled transpose, 64x64 tiles, explicit load/store batching.
// tile[64][66]: even stride -> aligned float2 smem ops (proven pattern).
// ---------------------------------------------------------------------------
template<int ROWS, int COLS>
__global__ __launch_bounds__(256) void tr64_kernel(const float* __restrict__ in,
                                                   float* __restrict__ out) {
    __shared__ float tile[64][66];
    const int bx = blockIdx.x * 64;           // column base (in)
    const int by = blockIdx.y * 64;           // row base (in)
    const int t  = threadIdx.x;

    {
        const int tx = t & 31;                // float2 index across 64 cols
        const int ty = t >> 5;                // 8 rows per step, 8 steps
        float2 v[8];
#pragma unroll
        for (int j = 0; j < 8; ++j)           // ALL loads first (MLP_p1 = 8)
            v[j] = *reinterpret_cast<const float2*>(
                in + (size_t)(by + ty + j * 8) * COLS + bx + tx * 2);
#pragma unroll
        for (int j = 0; j < 8; ++j)           // then all smem stores
            *reinterpret_cast<float2*>(&tile[ty + j * 8][tx * 2]) = v[j];
    }
    __syncthreads();
    {
        const int tx = t & 15;                // float2 index (half of 32)
        const int ty = t >> 4;                // 16 out-rows per step
        float2 v[8];
#pragma unroll
        for (int j = 0; j < 4; ++j) {         // ALL smem loads first
            const int r = ty + j * 16;
#pragma unroll
            for (int h = 0; h < 2; ++h) {
                const int c2 = tx + 16 * h;
                v[j * 2 + h].x = tile[c2 * 2 + 0][r];
                v[j * 2 + h].y = tile[c2 * 2 + 1][r];
            }
        }
#pragma unroll
        for (int j = 0; j < 4; ++j) {         // then all gmem stores
            const int r = ty + j * 16;
#pragma unroll
            for (int h = 0; h < 2; ++h) {
                const int c2 = tx + 16 * h;
                *reinterpret_cast<float2*>(
                    out + (size_t)(bx + r) * ROWS + by + c2 * 2) = v[j * 2 + h];
            }
        }
    }
}

// ---------------------------------------------------------------------------
// Fused 30-layer ODE. One CTA per channel p, 256 threads.
// Thread t owns (cij=t, b=0..15) as 8 packed pairs; x1 and z in registers.
// One __syncthreads per layer; parity-trick shuffle trees (7 + 4 shfl).
// ---------------------------------------------------------------------------
__global__ __launch_bounds__(256, 4) void ode_kernel(
    const float* __restrict__ xt,        // [HW][BC]
    const float* __restrict__ dtg,       // [NL]
    const float* __restrict__ mats,      // [NL][256]
    const float* __restrict__ gamma,     // [HW]
    const float* __restrict__ beta,      // [HW]
    float* __restrict__ yt)              // [HW][BC]
{
    __shared__ float4 lay[NL];           // {c1_l, A_{l+1}, 6*dt_l*A_{l+1}, eps*A_l^2}
    __shared__ float  red[2][16];        // interleaved s0,q0,s1,q1,... per warp
    __shared__ float  sm_alpha;

    const int p = blockIdx.x;
    const int t = threadIdx.x;
    const int lane = t & 31;
    const int wid  = t >> 5;

    // --- per-layer scalar precompute ---
    if (t < NL) {
        float d = dtg[t];
        d = fminf(fmaxf(d, 0.0f), 6.0f);
        lay[t].x = 1.0f - d;             // c1
        lay[t].y = d;                    // stash dt
    }
    __syncthreads();
    if (t == 0) {
        float A = 1.0f;                  // 1/alpha running
        float P = 1.0f;                  // alpha running (prod c1)
        for (int l = 0; l < NL; ++l) {
            const float c1 = lay[l].x;
            const float d  = lay[l].y;
            const float eps = 1e-5f * A * A;
            const float An = __fdividef(A, c1);
            P *= c1;
            lay[l] = make_float4(c1, An, 6.0f * d * An, eps);
            A = An;
        }
        sm_alpha = P;
    }

    const float gm = gamma[p];
    const float bt = beta[p];
    const float* __restrict__ xp = xt + (size_t)p * BC + t;
    const float* __restrict__ mp = mats + t;

    // --- load x1 to registers, init z̃_1 = (1+m_0)*x1 ---
    float mt = mp[0];
    u64 x1[8], z[8];
#pragma unroll
    for (int u = 0; u < 8; ++u) {
        const float a = xp[(2 * u) * 256];
        const float b = xp[(2 * u + 1) * 256];
        x1[u] = pk2(a, b);
        z[u]  = pk2(fmaf(mt, a, a), fmaf(mt, b, b));
    }
    __syncthreads();                      // covers lay[] / sm_alpha from t==0

    for (int l = 0; l < NL; ++l) {
        const float4 L = lay[l];          // LDS.128 broadcast
        const float mnx = (l < NL - 1) ? mp[(l + 1) * 256] : 1.0f;
        const float kps = fmaf(-L.x, mt, mnx) * L.y;   // (m' - c1*m) * A_{l+1}
        mt = mnx;
        const u64 kp   = pk2(kps, kps);
        const u64 dt6p = pk2(L.z, L.z);
        const int par  = l & 1;

        // stats on z̃ (packed accumulate)
        u64 s2 = 0ull, q2 = 0ull;
#pragma unroll
        for (int u = 0; u < 8; ++u) {
            s2 = add2(s2, z[u]);
            q2 = fma2(z[u], z[u], q2);
        }
        float sx, sy, qx, qy;
        upk2(s2, sx, sy); upk2(q2, qx, qy);
        const float s = sx + sy, q = qx + qy;

        // parity-merged warp butterfly: 7 shfl instead of 10.
        const float sn = __shfl_xor_sync(0xffffffffu, s, 1);
        const float qn = __shfl_xor_sync(0xffffffffu, q, 1);
        float v = (lane & 1) ? (q + qn) : (s + sn);
#pragma unroll
        for (int o = 2; o <= 16; o <<= 1)
            v += __shfl_xor_sync(0xffffffffu, v, o);
        // even lanes: warp S, odd lanes: warp Q
        if (lane < 2) red[par][wid * 2 + lane] = v;   // s at even idx, q at odd
        __syncthreads();                  // the ONLY barrier this layer

        // final reduce over 16 interleaved partials: 4 shfl.
        float w = red[par][lane & 15];
#pragma unroll
        for (int o = 2; o <= 8; o <<= 1)
            w += __shfl_xor_sync(0xffffffffu, w, o);
        const float wx = __shfl_xor_sync(0xffffffffu, w, 1);
        const float S = (lane & 1) ? wx : w;
        const float Q = (lane & 1) ? w : wx;

        const float inv = 1.0f / 4096.0f;
        const float mu  = S * inv;
        const float va  = fmaf(-mu, mu, Q * inv);
        const float ap  = gm * rsqrtf(va + L.w);
        const float a6  = ap * (1.0f / 6.0f);
        const float b6  = fmaf(-mu, ap, bt) * (1.0f / 6.0f);

#pragma unroll
        for (int u = 0; u < 8; ++u) {
            float zx, zy; upk2(z[u], zx, zy);
            const float rx = fma_sat(zx, a6, b6);      // relu6/6 via FFMA.SAT
            const float ry = fma_sat(zy, a6, b6);
            z[u] = fma2(dt6p, pk2(rx, ry), z[u]);
            z[u] = fma2(kp, x1[u], z[u]);
        }
    }

    // out = alpha * z̃_final  (layer 29 used m'=1 so z̃ holds y + x1)
    const float al = sm_alpha;
    const u64 al2 = pk2(al, al);
    float* __restrict__ yp = yt + (size_t)p * BC + t;
#pragma unroll
    for (int u = 0; u < 8; ++u) {
        float ox, oy; upk2(mul2(z[u], al2), ox, oy);
        yp[(2 * u) * 256]     = ox;
        yp[(2 * u + 1) * 256] = oy;
    }
}

// ---------------------------------------------------------------------------
extern "C" void kernel_launch(void* const* d_in, const int* in_sizes, int n_in,
                              void* d_out, int out_size) {
    const float* x   = (const float*)d_in[0];   // [16,256,32,32]
    const float* dt  = (const float*)d_in[1];   // [30,1]
    const float* mat = (const float*)d_in[2];   // [30,1,1,16,16]
    const float* gm  = (const float*)d_in[3];   // [1024]
    const float* bt  = (const float*)d_in[4];   // [1024]
    float* out = (float*)d_out;                 // [16,256,32,32]

    float *xt, *yt;
    cudaGetSymbolAddress((void**)&xt, g_xt);
    cudaGetSymbolAddress((void**)&yt, g_yt);

    // x: [4096 x 1024] -> xt: [1024 x 4096]
    tr64_kernel<BC, HW><<<dim3(HW / 64, BC / 64), 256>>>(x, xt);
    // fused 30-layer ODE, one CTA per channel
    ode_kernel<<<HW, 256>>>(xt, dt, mat, gm, bt, yt);
    // yt: [1024 x 4096] -> out: [4096 x 1024]
    tr64_kernel<HW, BC><<<dim3(BC / 64, HW / 64), 256>>>(yt, out);
}